// round 13
// baseline (speedup 1.0000x reference)
#include <cuda_runtime.h>
#include <cuda_fp16.h>

// Problem constants (fixed by the reference generator)
#define NN   10000
#define BB   2
#define FF   128
#define DD   128
#define EPN  33             // edges per node (DEG+1), contiguous per src node
#define ROWS (BB * NN)

// GEMM (R12 config — best measured): 125 blocks x 512 threads
#define GTPB   512
#define GNBLK  125
#define NPB    80                    // nodes per block
#define GBM    160                   // rows per block (80 x 2 batches)
#define XPITCH 136
#define WPITCH 136
#define HPITCH 136
#define XS_BYTES  (GBM * XPITCH * 2)             // 43520
#define WS_BYTES  (128 * WPITCH * 2)             // 34816
#define HS_BYTES  (GBM * HPITCH * 2)             // 43520
#define SD_BYTES  (2 * 8 * GBM * 4)              // 10240
#define GEMM_SMEM (XS_BYTES + WS_BYTES + HS_BYTES + SD_BYTES)   // 132096

// Scratch (device globals — no cudaMalloc allowed)
__device__ uint4 g_hx[NN * 32];     // h both batches interleaved, fp16
__device__ float g_ss[NN * 2];      // s packed [node][batch]
__device__ float g_dd[NN * 2];      // d packed [node][batch]

__device__ __forceinline__ unsigned packh2(float lo, float hi) {
    __half2 h = __floats2half2_rn(lo, hi);
    return *(unsigned*)&h;
}
__device__ __forceinline__ void ffma2(unsigned long long& acc,
                                      unsigned long long a,
                                      unsigned long long b) {
    asm("fma.rn.f32x2 %0, %1, %2, %0;" : "+l"(acc) : "l"(a), "l"(b));
}
__device__ __forceinline__ unsigned long long packf2(float lo, float hi) {
    unsigned long long v;
    asm("mov.b64 %0, {%1, %2};" : "=l"(v) : "f"(lo), "f"(hi));
    return v;
}
__device__ __forceinline__ float2 unpackf2(unsigned long long v) {
    float2 r;
    asm("mov.b64 {%0, %1}, %2;" : "=f"(r.x), "=f"(r.y) : "l"(v));
    return r;
}
__device__ __forceinline__ unsigned smem_u32(const void* p) {
    return (unsigned)__cvta_generic_to_shared(p);
}
__device__ __forceinline__ void ldmx4(unsigned& r0, unsigned& r1,
                                      unsigned& r2, unsigned& r3, unsigned a) {
    asm volatile("ldmatrix.sync.aligned.m8n8.x4.shared.b16 {%0,%1,%2,%3}, [%4];"
                 : "=r"(r0), "=r"(r1), "=r"(r2), "=r"(r3) : "r"(a));
}
__device__ __forceinline__ void ldmx2t(unsigned& r0, unsigned& r1, unsigned a) {
    asm volatile("ldmatrix.sync.aligned.m8n8.x2.trans.shared.b16 {%0,%1}, [%2];"
                 : "=r"(r0), "=r"(r1) : "r"(a));
}

// leaky_relu(0.2) -> clip[-2,2] -> exp
__device__ __forceinline__ float gat_w(float sc) {
    sc = (sc > 0.0f) ? sc : 0.2f * sc;
    return expf(fminf(fmaxf(sc, -2.0f), 2.0f));
}

extern __shared__ char smem_raw[];

// ---------------------------------------------------------------------------
// Kernel A (R12 GEMM, unchanged): h = X @ W via mma.sync + fused s/d.
// ---------------------------------------------------------------------------
__global__ __launch_bounds__(GTPB)
void gemm_sd_kernel(const float* __restrict__ inputs,
                    const float* __restrict__ W,
                    const float* __restrict__ W_attn) {
    __half (*Xs)[XPITCH] = (__half(*)[XPITCH])smem_raw;
    __half (*Ws)[WPITCH] = (__half(*)[WPITCH])(smem_raw + XS_BYTES);
    __half (*Hs)[HPITCH] = (__half(*)[HPITCH])(smem_raw + XS_BYTES + WS_BYTES);
    float* sd_s = (float*)(smem_raw + XS_BYTES + WS_BYTES + HS_BYTES);
    float* sd_d = sd_s + 8 * GBM;

    const int t    = threadIdx.x;
    const int lane = t & 31;
    const int w    = t >> 5;
    const int c8   = w & 7;
    const int mh   = w >> 3;
    const int nb   = blockIdx.x;
    const int tg   = lane & 3;
    const int wcol = c8 * 16;

#pragma unroll
    for (int i = 0; i < 10; ++i) {
        int idx = t + i * GTPB;
        int row = idx >> 5, c4 = idx & 31;
        int gr = (row < NPB) ? (nb * NPB + row)
                             : (NN + nb * NPB + row - NPB);
        float4 v = ((const float4*)inputs)[gr * 32 + c4];
        *(uint2*)&Xs[row][c4 * 4] =
            make_uint2(packh2(v.x, v.y), packh2(v.z, v.w));
    }
#pragma unroll
    for (int i = 0; i < 8; ++i) {
        int idx = t + i * GTPB;
        int k = idx >> 5, c4 = idx & 31;
        float4 v = ((const float4*)W)[idx];
        *(uint2*)&Ws[k][c4 * 4] =
            make_uint2(packh2(v.x, v.y), packh2(v.z, v.w));
    }
    __syncthreads();

    unsigned bf[2][8][2];
    {
        const int l16 = lane & 15;
#pragma unroll
        for (int nt = 0; nt < 2; ++nt)
#pragma unroll
            for (int kt = 0; kt < 8; ++kt) {
                unsigned a = smem_u32(&Ws[kt * 16 + l16][wcol + nt * 8]);
                ldmx2t(bf[nt][kt][0], bf[nt][kt][1], a);
            }
    }
    float as[2][2], ad[2][2];
#pragma unroll
    for (int nt = 0; nt < 2; ++nt) {
        const int c = wcol + nt * 8 + tg * 2;
        as[nt][0] = W_attn[c];       as[nt][1] = W_attn[c + 1];
        ad[nt][0] = W_attn[DD + c];  ad[nt][1] = W_attn[DD + c + 1];
    }

    const int arow = (lane & 7) + (lane & 8);
    const int acol = (lane >> 4) << 3;
    const int g    = lane >> 2;

#pragma unroll 1
    for (int mt = mh * 5; mt < mh * 5 + 5; ++mt) {
        float accE[2][4], accO[2][4];
#pragma unroll
        for (int nt = 0; nt < 2; ++nt)
#pragma unroll
            for (int i = 0; i < 4; ++i) { accE[nt][i] = 0.f; accO[nt][i] = 0.f; }

#pragma unroll
        for (int kt = 0; kt < 8; ++kt) {
            unsigned a0, a1, a2, a3;
            unsigned addr = smem_u32(&Xs[mt * 16 + arow][kt * 16 + acol]);
            ldmx4(a0, a1, a2, a3, addr);
            float (*acc)[4] = (kt & 1) ? accO : accE;
#pragma unroll
            for (int nt = 0; nt < 2; ++nt) {
                asm volatile(
                    "mma.sync.aligned.m16n8k16.row.col.f32.f16.f16.f32 "
                    "{%0,%1,%2,%3}, {%4,%5,%6,%7}, {%8,%9}, {%0,%1,%2,%3};"
                    : "+f"(acc[nt][0]), "+f"(acc[nt][1]),
                      "+f"(acc[nt][2]), "+f"(acc[nt][3])
                    : "r"(a0), "r"(a1), "r"(a2), "r"(a3),
                      "r"(bf[nt][kt][0]), "r"(bf[nt][kt][1]));
            }
        }

        float acc[2][4];
#pragma unroll
        for (int nt = 0; nt < 2; ++nt)
#pragma unroll
            for (int i = 0; i < 4; ++i) acc[nt][i] = accE[nt][i] + accO[nt][i];

#pragma unroll
        for (int nt = 0; nt < 2; ++nt) {
            const int col = wcol + nt * 8 + tg * 2;
            *(unsigned*)&Hs[mt * 16 + g][col]     = packh2(acc[nt][0], acc[nt][1]);
            *(unsigned*)&Hs[mt * 16 + g + 8][col] = packh2(acc[nt][2], acc[nt][3]);
        }

        float ps0 = 0.f, pd0 = 0.f, ps1 = 0.f, pd1 = 0.f;
#pragma unroll
        for (int nt = 0; nt < 2; ++nt) {
            ps0 = fmaf(acc[nt][0], as[nt][0], fmaf(acc[nt][1], as[nt][1], ps0));
            pd0 = fmaf(acc[nt][0], ad[nt][0], fmaf(acc[nt][1], ad[nt][1], pd0));
            ps1 = fmaf(acc[nt][2], as[nt][0], fmaf(acc[nt][3], as[nt][1], ps1));
            pd1 = fmaf(acc[nt][2], ad[nt][0], fmaf(acc[nt][3], ad[nt][1], pd1));
        }
#pragma unroll
        for (int off = 1; off <= 2; off <<= 1) {
            ps0 += __shfl_xor_sync(0xFFFFFFFFu, ps0, off);
            pd0 += __shfl_xor_sync(0xFFFFFFFFu, pd0, off);
            ps1 += __shfl_xor_sync(0xFFFFFFFFu, ps1, off);
            pd1 += __shfl_xor_sync(0xFFFFFFFFu, pd1, off);
        }
        if (tg == 0) {
            sd_s[c8 * GBM + mt * 16 + g]     = ps0;
            sd_d[c8 * GBM + mt * 16 + g]     = pd0;
            sd_s[c8 * GBM + mt * 16 + g + 8] = ps1;
            sd_d[c8 * GBM + mt * 16 + g + 8] = pd1;
        }
    }
    __syncthreads();

#pragma unroll
    for (int i = 0; i < 5; ++i) {
        int e  = t + i * GTPB;
        int nl = e >> 5, grp = e & 31;
        uint2 b0 = *(const uint2*)&Hs[nl][grp * 4];
        uint2 b1 = *(const uint2*)&Hs[nl + NPB][grp * 4];
        g_hx[(nb * NPB + nl) * 32 + grp] = make_uint4(b0.x, b0.y, b1.x, b1.y);
    }
    if (t < GBM) {
        float s = 0.f, d = 0.f;
#pragma unroll
        for (int i = 0; i < 8; ++i) {
            s += sd_s[i * GBM + t];
            d += sd_d[i * GBM + t];
        }
        const int b    = (t < NPB) ? 0 : 1;
        const int node = nb * NPB + t - b * NPB;
        g_ss[node * 2 + b] = s;
        g_dd[node * 2 + b] = d;
    }
}

// ---------------------------------------------------------------------------
// Kernel B: TWO nodes per warp — interleaved gather streams double per-warp
// MLP (8 LDG.128 in flight) at similar warp count. 8 warps/block, 16 nodes.
// ---------------------------------------------------------------------------
__global__ __launch_bounds__(256)
void gat_agg_kernel(const int* __restrict__ edges,
                    float* __restrict__ out) {
    __shared__ int    offs[8][2][EPN];
    __shared__ float4 wpr[8][2][EPN];

    const int t    = threadIdx.x;
    const int lane = t & 31;
    const int wi   = t >> 5;
    const int nA   = blockIdx.x * 16 + wi * 2;
    const int nB   = nA + 1;

    // --- Phase 1: scores for both nodes (lane = edge index) ---
    const int2 eA = __ldg(&((const int2*)edges)[nA * EPN + lane]);
    const int2 eB = __ldg(&((const int2*)edges)[nB * EPN + lane]);
    const float2 svA = __ldg(&((const float2*)g_ss)[nA]);
    const float2 svB = __ldg(&((const float2*)g_ss)[nB]);
    const float2 dvA = __ldg(&((const float2*)g_dd)[eA.y]);
    const float2 dvB = __ldg(&((const float2*)g_dd)[eB.y]);

    const float w0A = gat_w(svA.x + dvA.x), w1A = gat_w(svA.y + dvA.y);
    const float w0B = gat_w(svB.x + dvB.x), w1B = gat_w(svB.y + dvB.y);

    // edge 32 for both (broadcast loads)
    const int d32A = __ldg(&edges[(nA * EPN + 32) * 2 + 1]);
    const int d32B = __ldg(&edges[(nB * EPN + 32) * 2 + 1]);
    const float2 dxA = __ldg(&((const float2*)g_dd)[d32A]);
    const float2 dxB = __ldg(&((const float2*)g_dd)[d32B]);
    const float w032A = gat_w(svA.x + dxA.x), w132A = gat_w(svA.y + dxA.y);
    const float w032B = gat_w(svB.x + dxB.x), w132B = gat_w(svB.y + dxB.y);

    // denominators (batch 0), two interleaved reductions
    float dnA = w0A, dnB = w0B;
#pragma unroll
    for (int off = 16; off > 0; off >>= 1) {
        dnA += __shfl_xor_sync(0xFFFFFFFFu, dnA, off);
        dnB += __shfl_xor_sync(0xFFFFFFFFu, dnB, off);
    }
    const float invA = 1.0f / (dnA + w032A);
    const float invB = 1.0f / (dnB + w032B);

    offs[wi][0][lane] = eA.y * (int)sizeof(uint4) * 32;
    offs[wi][1][lane] = eB.y * (int)sizeof(uint4) * 32;
    wpr[wi][0][lane] = make_float4(w0A * invA, w0A * invA, w1A * invA, w1A * invA);
    wpr[wi][1][lane] = make_float4(w0B * invB, w0B * invB, w1B * invB, w1B * invB);
    if (lane == 0) {
        offs[wi][0][32] = d32A * (int)sizeof(uint4) * 32;
        offs[wi][1][32] = d32B * (int)sizeof(uint4) * 32;
        wpr[wi][0][32] = make_float4(w032A * invA, w032A * invA,
                                     w132A * invA, w132A * invA);
        wpr[wi][1][32] = make_float4(w032B * invB, w032B * invB,
                                     w132B * invB, w132B * invB);
    }
    __syncwarp();

    // --- Phase 2: interleaved gathers (8 LDG.128 in flight per warp) ---
    const char* hbase = (const char*)g_hx + lane * 16;
    unsigned long long aAA = 0ull, aAB = 0ull;   // node A: feats(0,1),(2,3)
    unsigned long long aBA = 0ull, aBB = 0ull;   // node B

#pragma unroll
    for (int eb = 0; eb < 32; eb += 4) {
        int   ofA[4], ofB[4];
        uint4 vA[4], vB[4];
#pragma unroll
        for (int k = 0; k < 4; ++k) {
            ofA[k] = offs[wi][0][eb + k];
            ofB[k] = offs[wi][1][eb + k];
        }
#pragma unroll
        for (int k = 0; k < 4; ++k) {
            vA[k] = *(const uint4*)(hbase + ofA[k]);
            vB[k] = *(const uint4*)(hbase + ofB[k]);
        }
#pragma unroll
        for (int k = 0; k < 4; ++k) {
            {
                const float4 wp = wpr[wi][0][eb + k];
                const unsigned long long c0p = packf2(wp.x, wp.y);
                const unsigned long long c1p = packf2(wp.z, wp.w);
                float2 f0a = __half22float2(*(__half2*)&vA[k].x);
                float2 f0b = __half22float2(*(__half2*)&vA[k].y);
                float2 f1a = __half22float2(*(__half2*)&vA[k].z);
                float2 f1b = __half22float2(*(__half2*)&vA[k].w);
                ffma2(aAA, packf2(f0a.x, f0a.y), c0p);
                ffma2(aAA, packf2(f1a.x, f1a.y), c1p);
                ffma2(aAB, packf2(f0b.x, f0b.y), c0p);
                ffma2(aAB, packf2(f1b.x, f1b.y), c1p);
            }
            {
                const float4 wp = wpr[wi][1][eb + k];
                const unsigned long long c0p = packf2(wp.x, wp.y);
                const unsigned long long c1p = packf2(wp.z, wp.w);
                float2 f0a = __half22float2(*(__half2*)&vB[k].x);
                float2 f0b = __half22float2(*(__half2*)&vB[k].y);
                float2 f1a = __half22float2(*(__half2*)&vB[k].z);
                float2 f1b = __half22float2(*(__half2*)&vB[k].w);
                ffma2(aBA, packf2(f0a.x, f0a.y), c0p);
                ffma2(aBA, packf2(f1a.x, f1a.y), c1p);
                ffma2(aBB, packf2(f0b.x, f0b.y), c0p);
                ffma2(aBB, packf2(f1b.x, f1b.y), c1p);
            }
        }
    }
    {   // edge 32, both nodes
        const uint4 vA = *(const uint4*)(hbase + offs[wi][0][32]);
        const uint4 vB = *(const uint4*)(hbase + offs[wi][1][32]);
        {
            const float4 wp = wpr[wi][0][32];
            const unsigned long long c0p = packf2(wp.x, wp.y);
            const unsigned long long c1p = packf2(wp.z, wp.w);
            float2 f0a = __half22float2(*(__half2*)&vA.x);
            float2 f0b = __half22float2(*(__half2*)&vA.y);
            float2 f1a = __half22float2(*(__half2*)&vA.z);
            float2 f1b = __half22float2(*(__half2*)&vA.w);
            ffma2(aAA, packf2(f0a.x, f0a.y), c0p);
            ffma2(aAA, packf2(f1a.x, f1a.y), c1p);
            ffma2(aAB, packf2(f0b.x, f0b.y), c0p);
            ffma2(aAB, packf2(f1b.x, f1b.y), c1p);
        }
        {
            const float4 wp = wpr[wi][1][32];
            const unsigned long long c0p = packf2(wp.x, wp.y);
            const unsigned long long c1p = packf2(wp.z, wp.w);
            float2 f0a = __half22float2(*(__half2*)&vB.x);
            float2 f0b = __half22float2(*(__half2*)&vB.y);
            float2 f1a = __half22float2(*(__half2*)&vB.z);
            float2 f1b = __half22float2(*(__half2*)&vB.w);
            ffma2(aBA, packf2(f0a.x, f0a.y), c0p);
            ffma2(aBA, packf2(f1a.x, f1a.y), c1p);
            ffma2(aBB, packf2(f0b.x, f0b.y), c0p);
            ffma2(aBB, packf2(f1b.x, f1b.y), c1p);
        }
    }

    {
        const float2 rA = unpackf2(aAA);
        const float2 rB = unpackf2(aAB);
        const float4 r = make_float4(rA.x, rA.y, rB.x, rB.y);
        ((float4*)(out + nA * DD))[lane]           = r;
        ((float4*)(out + NN * DD + nA * DD))[lane] = r;
    }
    {
        const float2 rA = unpackf2(aBA);
        const float2 rB = unpackf2(aBB);
        const float4 r = make_float4(rA.x, rA.y, rB.x, rB.y);
        ((float4*)(out + nB * DD))[lane]           = r;
        ((float4*)(out + NN * DD + nB * DD))[lane] = r;
    }
}

// ---------------------------------------------------------------------------
extern "C" void kernel_launch(void* const* d_in, const int* in_sizes, int n_in,
                              void* d_out, int out_size) {
    const float* inputs = (const float*)d_in[0];
    const float* W      = (const float*)d_in[1];
    const float* W_attn = (const float*)d_in[2];
    const int*   edges  = (const int*)d_in[3];
    float*       out    = (float*)d_out;

    cudaFuncSetAttribute(gemm_sd_kernel,
                         cudaFuncAttributeMaxDynamicSharedMemorySize, GEMM_SMEM);

    gemm_sd_kernel<<<GNBLK, GTPB, GEMM_SMEM>>>(inputs, W, W_attn);
    gat_agg_kernel<<<NN / 16, 256>>>(edges, out);
}

// round 14
// speedup vs baseline: 1.0919x; 1.0919x over previous
#include <cuda_runtime.h>
#include <cuda_fp16.h>

// Problem constants (fixed by the reference generator)
#define NN   10000
#define BB   2
#define FF   128
#define DD   128
#define EPN  33             // edges per node (DEG+1), contiguous per src node
#define ROWS (BB * NN)

// GEMM: GBM=144 (72 nodes x 2 batches) -> 139 blocks, single wave on 148 SMs
// (was 125 blocks: 16% of DRAM-fetch SMs idle during the staging phase).
#define GTPB   512
#define NPB    72                    // nodes per block
#define GBM    144                   // rows per block
#define GNBLK  ((NN + NPB - 1) / NPB)    // 139
#define NMT    (GBM / 16)            // 9 m-tiles
#define XPITCH 136
#define WPITCH 136
#define HPITCH 136
#define XS_BYTES  (GBM * XPITCH * 2)             // 39168
#define WS_BYTES  (128 * WPITCH * 2)             // 34816
#define HS_BYTES  (GBM * HPITCH * 2)             // 39168
#define SD_BYTES  (2 * 8 * GBM * 4)              // 9216
#define GEMM_SMEM (XS_BYTES + WS_BYTES + HS_BYTES + SD_BYTES)   // 122368

// Scratch (device globals — no cudaMalloc allowed)
__device__ uint4 g_hx[NN * 32];     // h both batches interleaved, fp16
__device__ float g_ss[NN * 2];      // s packed [node][batch]
__device__ float g_dd[NN * 2];      // d packed [node][batch]

__device__ __forceinline__ unsigned packh2(float lo, float hi) {
    __half2 h = __floats2half2_rn(lo, hi);
    return *(unsigned*)&h;
}
__device__ __forceinline__ void ffma2(unsigned long long& acc,
                                      unsigned long long a,
                                      unsigned long long b) {
    asm("fma.rn.f32x2 %0, %1, %2, %0;" : "+l"(acc) : "l"(a), "l"(b));
}
__device__ __forceinline__ unsigned long long packf2(float lo, float hi) {
    unsigned long long v;
    asm("mov.b64 %0, {%1, %2};" : "=l"(v) : "f"(lo), "f"(hi));
    return v;
}
__device__ __forceinline__ float2 unpackf2(unsigned long long v) {
    float2 r;
    asm("mov.b64 {%0, %1}, %2;" : "=f"(r.x), "=f"(r.y) : "l"(v));
    return r;
}
__device__ __forceinline__ unsigned smem_u32(const void* p) {
    return (unsigned)__cvta_generic_to_shared(p);
}
__device__ __forceinline__ void ldmx4(unsigned& r0, unsigned& r1,
                                      unsigned& r2, unsigned& r3, unsigned a) {
    asm volatile("ldmatrix.sync.aligned.m8n8.x4.shared.b16 {%0,%1,%2,%3}, [%4];"
                 : "=r"(r0), "=r"(r1), "=r"(r2), "=r"(r3) : "r"(a));
}
__device__ __forceinline__ void ldmx2t(unsigned& r0, unsigned& r1, unsigned a) {
    asm volatile("ldmatrix.sync.aligned.m8n8.x2.trans.shared.b16 {%0,%1}, [%2];"
                 : "=r"(r0), "=r"(r1) : "r"(a));
}

extern __shared__ char smem_raw[];

// ---------------------------------------------------------------------------
// Kernel A: h = X @ W via mma.sync.m16n8k16 + fused s/d.
// 512 threads = 16 warps: c8 = w&7 -> cols [c8*16,+16), mh = w>>3 -> m-tiles
// (mh=0: tiles 0..4, mh=1: tiles 5..8). Rows 0..71 = batch0 nodes,
// rows 72..143 = batch1 same nodes. Last block: phantom nodes clamped/guarded.
// ---------------------------------------------------------------------------
__global__ __launch_bounds__(GTPB)
void gemm_sd_kernel(const float* __restrict__ inputs,
                    const float* __restrict__ W,
                    const float* __restrict__ W_attn) {
    __half (*Xs)[XPITCH] = (__half(*)[XPITCH])smem_raw;
    __half (*Ws)[WPITCH] = (__half(*)[WPITCH])(smem_raw + XS_BYTES);
    __half (*Hs)[HPITCH] = (__half(*)[HPITCH])(smem_raw + XS_BYTES + WS_BYTES);
    float* sd_s = (float*)(smem_raw + XS_BYTES + WS_BYTES + HS_BYTES);
    float* sd_d = sd_s + 8 * GBM;

    const int t    = threadIdx.x;
    const int lane = t & 31;
    const int w    = t >> 5;
    const int c8   = w & 7;
    const int mh   = w >> 3;
    const int nb   = blockIdx.x;
    const int tg   = lane & 3;
    const int wcol = c8 * 16;

    // --- Stage X: 144 rows x 32 float4 = 4608 = 9 its x 512 threads ---
#pragma unroll
    for (int i = 0; i < 9; ++i) {
        int idx = t + i * GTPB;
        int row = idx >> 5, c4 = idx & 31;
        int node = nb * NPB + ((row < NPB) ? row : row - NPB);
        if (node >= NN) node = NN - 1;          // clamp (last block)
        int gr = (row < NPB) ? node : NN + node;
        float4 v = ((const float4*)inputs)[gr * 32 + c4];
        *(uint2*)&Xs[row][c4 * 4] =
            make_uint2(packh2(v.x, v.y), packh2(v.z, v.w));
    }
    // --- Stage W (128x128 fp32 -> fp16) ---
#pragma unroll
    for (int i = 0; i < 8; ++i) {
        int idx = t + i * GTPB;
        int k = idx >> 5, c4 = idx & 31;
        float4 v = ((const float4*)W)[idx];
        *(uint2*)&Ws[k][c4 * 4] =
            make_uint2(packh2(v.x, v.y), packh2(v.z, v.w));
    }
    __syncthreads();

    // --- B fragments via ldmatrix.x2.trans ---
    unsigned bf[2][8][2];
    {
        const int l16 = lane & 15;
#pragma unroll
        for (int nt = 0; nt < 2; ++nt)
#pragma unroll
            for (int kt = 0; kt < 8; ++kt) {
                unsigned a = smem_u32(&Ws[kt * 16 + l16][wcol + nt * 8]);
                ldmx2t(bf[nt][kt][0], bf[nt][kt][1], a);
            }
    }
    float as[2][2], ad[2][2];
#pragma unroll
    for (int nt = 0; nt < 2; ++nt) {
        const int c = wcol + nt * 8 + tg * 2;
        as[nt][0] = W_attn[c];       as[nt][1] = W_attn[c + 1];
        ad[nt][0] = W_attn[DD + c];  ad[nt][1] = W_attn[DD + c + 1];
    }

    const int arow = (lane & 7) + (lane & 8);
    const int acol = (lane >> 4) << 3;
    const int g    = lane >> 2;

    // --- Main loop: mh=0 -> tiles [0,5), mh=1 -> tiles [5,9) ---
    const int mt0 = mh * 5;
    const int mt1 = (mh == 0) ? 5 : NMT;
#pragma unroll 1
    for (int mt = mt0; mt < mt1; ++mt) {
        float accE[2][4], accO[2][4];
#pragma unroll
        for (int nt = 0; nt < 2; ++nt)
#pragma unroll
            for (int i = 0; i < 4; ++i) { accE[nt][i] = 0.f; accO[nt][i] = 0.f; }

#pragma unroll
        for (int kt = 0; kt < 8; ++kt) {
            unsigned a0, a1, a2, a3;
            unsigned addr = smem_u32(&Xs[mt * 16 + arow][kt * 16 + acol]);
            ldmx4(a0, a1, a2, a3, addr);
            float (*acc)[4] = (kt & 1) ? accO : accE;
#pragma unroll
            for (int nt = 0; nt < 2; ++nt) {
                asm volatile(
                    "mma.sync.aligned.m16n8k16.row.col.f32.f16.f16.f32 "
                    "{%0,%1,%2,%3}, {%4,%5,%6,%7}, {%8,%9}, {%0,%1,%2,%3};"
                    : "+f"(acc[nt][0]), "+f"(acc[nt][1]),
                      "+f"(acc[nt][2]), "+f"(acc[nt][3])
                    : "r"(a0), "r"(a1), "r"(a2), "r"(a3),
                      "r"(bf[nt][kt][0]), "r"(bf[nt][kt][1]));
            }
        }

        float acc[2][4];
#pragma unroll
        for (int nt = 0; nt < 2; ++nt)
#pragma unroll
            for (int i = 0; i < 4; ++i) acc[nt][i] = accE[nt][i] + accO[nt][i];

        // --- Epilogue: h -> smem (conflict-free STS) ---
#pragma unroll
        for (int nt = 0; nt < 2; ++nt) {
            const int col = wcol + nt * 8 + tg * 2;
            *(unsigned*)&Hs[mt * 16 + g][col]     = packh2(acc[nt][0], acc[nt][1]);
            *(unsigned*)&Hs[mt * 16 + g + 8][col] = packh2(acc[nt][2], acc[nt][3]);
        }

        float ps0 = 0.f, pd0 = 0.f, ps1 = 0.f, pd1 = 0.f;
#pragma unroll
        for (int nt = 0; nt < 2; ++nt) {
            ps0 = fmaf(acc[nt][0], as[nt][0], fmaf(acc[nt][1], as[nt][1], ps0));
            pd0 = fmaf(acc[nt][0], ad[nt][0], fmaf(acc[nt][1], ad[nt][1], pd0));
            ps1 = fmaf(acc[nt][2], as[nt][0], fmaf(acc[nt][3], as[nt][1], ps1));
            pd1 = fmaf(acc[nt][2], ad[nt][0], fmaf(acc[nt][3], ad[nt][1], pd1));
        }
#pragma unroll
        for (int off = 1; off <= 2; off <<= 1) {
            ps0 += __shfl_xor_sync(0xFFFFFFFFu, ps0, off);
            pd0 += __shfl_xor_sync(0xFFFFFFFFu, pd0, off);
            ps1 += __shfl_xor_sync(0xFFFFFFFFu, ps1, off);
            pd1 += __shfl_xor_sync(0xFFFFFFFFu, pd1, off);
        }
        if (tg == 0) {
            sd_s[c8 * GBM + mt * 16 + g]     = ps0;
            sd_d[c8 * GBM + mt * 16 + g]     = pd0;
            sd_s[c8 * GBM + mt * 16 + g + 8] = ps1;
            sd_d[c8 * GBM + mt * 16 + g + 8] = pd1;
        }
    }
    __syncthreads();

    // --- Store phase: interleaved uint4, coalesced, node-guarded ---
#pragma unroll
    for (int i = 0; i < 5; ++i) {
        int e = t + i * GTPB;                    // 0..2303 valid
        if (e < NPB * 32) {
            int nl = e >> 5, grp = e & 31;
            int node = nb * NPB + nl;
            if (node < NN) {
                uint2 b0 = *(const uint2*)&Hs[nl][grp * 4];
                uint2 b1 = *(const uint2*)&Hs[nl + NPB][grp * 4];
                g_hx[node * 32 + grp] = make_uint4(b0.x, b0.y, b1.x, b1.y);
            }
        }
    }
    if (t < GBM) {
        float s = 0.f, d = 0.f;
#pragma unroll
        for (int i = 0; i < 8; ++i) {
            s += sd_s[i * GBM + t];
            d += sd_d[i * GBM + t];
        }
        const int b    = (t < NPB) ? 0 : 1;
        const int node = nb * NPB + t - b * NPB;
        if (node < NN) {
            g_ss[node * 2 + b] = s;
            g_dd[node * 2 + b] = d;
        }
    }
}

// ---------------------------------------------------------------------------
// Kernel B (R12 verbatim — measured optimum: 1250 blocks, ~60% occ, 4-deep
// load batching, packed d gathers; runs at the ~12.6 TB/s L2 cap).
// ---------------------------------------------------------------------------
__global__ __launch_bounds__(256)
void gat_agg_kernel(const int* __restrict__ edges,
                    float* __restrict__ out) {
    __shared__ int    offs[8][EPN];
    __shared__ float4 wpr[8][EPN];

    const int t    = threadIdx.x;
    const int lane = t & 31;
    const int wi   = t >> 5;
    const int n    = blockIdx.x * 8 + wi;

    const int2 e2  = __ldg(&((const int2*)edges)[n * EPN + lane]);
    const int dstv = e2.y;
    const float2 sv = __ldg(&((const float2*)g_ss)[n]);

    const float2 dv = __ldg(&((const float2*)g_dd)[dstv]);
    float sc0 = sv.x + dv.x;
    float sc1 = sv.y + dv.y;
    sc0 = (sc0 > 0.0f) ? sc0 : 0.2f * sc0;
    sc1 = (sc1 > 0.0f) ? sc1 : 0.2f * sc1;
    const float w0v = expf(fminf(fmaxf(sc0, -2.0f), 2.0f));
    const float w1v = expf(fminf(fmaxf(sc1, -2.0f), 2.0f));

    const int d32 = __ldg(&edges[(n * EPN + 32) * 2 + 1]);
    const float2 dx = __ldg(&((const float2*)g_dd)[d32]);
    float sx0 = sv.x + dx.x;
    float sx1 = sv.y + dx.y;
    sx0 = (sx0 > 0.0f) ? sx0 : 0.2f * sx0;
    sx1 = (sx1 > 0.0f) ? sx1 : 0.2f * sx1;
    const float w032 = expf(fminf(fmaxf(sx0, -2.0f), 2.0f));
    const float w132 = expf(fminf(fmaxf(sx1, -2.0f), 2.0f));

    float dn = w0v;
#pragma unroll
    for (int off = 16; off > 0; off >>= 1)
        dn += __shfl_xor_sync(0xFFFFFFFFu, dn, off);
    dn += w032;
    const float inv = 1.0f / dn;

    offs[wi][lane] = dstv * (int)sizeof(uint4) * 32;
    {
        const float a = w0v * inv, b = w1v * inv;
        wpr[wi][lane] = make_float4(a, a, b, b);
    }
    if (lane == 0) {
        offs[wi][32] = d32 * (int)sizeof(uint4) * 32;
        const float a = w032 * inv, b = w132 * inv;
        wpr[wi][32] = make_float4(a, a, b, b);
    }
    __syncwarp();

    const char* hbase = (const char*)g_hx + lane * 16;
    unsigned long long accA = 0ull, accB = 0ull;

#pragma unroll
    for (int eb = 0; eb < 32; eb += 4) {
        int    of[4];
        uint4  v[4];
        float4 wp[4];
#pragma unroll
        for (int k = 0; k < 4; ++k) of[k] = offs[wi][eb + k];
#pragma unroll
        for (int k = 0; k < 4; ++k) v[k] = *(const uint4*)(hbase + of[k]);
#pragma unroll
        for (int k = 0; k < 4; ++k) wp[k] = wpr[wi][eb + k];
#pragma unroll
        for (int k = 0; k < 4; ++k) {
            const unsigned long long c0p = packf2(wp[k].x, wp[k].y);
            const unsigned long long c1p = packf2(wp[k].z, wp[k].w);
            float2 f0a = __half22float2(*(__half2*)&v[k].x);
            float2 f0b = __half22float2(*(__half2*)&v[k].y);
            float2 f1a = __half22float2(*(__half2*)&v[k].z);
            float2 f1b = __half22float2(*(__half2*)&v[k].w);
            ffma2(accA, packf2(f0a.x, f0a.y), c0p);
            ffma2(accA, packf2(f1a.x, f1a.y), c1p);
            ffma2(accB, packf2(f0b.x, f0b.y), c0p);
            ffma2(accB, packf2(f1b.x, f1b.y), c1p);
        }
    }
    {   // edge 32
        const int of = offs[wi][32];
        const float4 wp = wpr[wi][32];
        const uint4 v = *(const uint4*)(hbase + of);
        const unsigned long long c0p = packf2(wp.x, wp.y);
        const unsigned long long c1p = packf2(wp.z, wp.w);
        float2 f0a = __half22float2(*(__half2*)&v.x);
        float2 f0b = __half22float2(*(__half2*)&v.y);
        float2 f1a = __half22float2(*(__half2*)&v.z);
        float2 f1b = __half22float2(*(__half2*)&v.w);
        ffma2(accA, packf2(f0a.x, f0a.y), c0p);
        ffma2(accA, packf2(f1a.x, f1a.y), c1p);
        ffma2(accB, packf2(f0b.x, f0b.y), c0p);
        ffma2(accB, packf2(f1b.x, f1b.y), c1p);
    }

    const float2 rA = unpackf2(accA);
    const float2 rB = unpackf2(accB);
    const float4 r = make_float4(rA.x, rA.y, rB.x, rB.y);
    ((float4*)(out + n * DD))[lane]           = r;
    ((float4*)(out + NN * DD + n * DD))[lane] = r;
}

// ---------------------------------------------------------------------------
extern "C" void kernel_launch(void* const* d_in, const int* in_sizes, int n_in,
                              void* d_out, int out_size) {
    const float* inputs = (const float*)d_in[0];
    const float* W      = (const float*)d_in[1];
    const float* W_attn = (const float*)d_in[2];
    const int*   edges  = (const int*)d_in[3];
    float*       out    = (float*)d_out;

    cudaFuncSetAttribute(gemm_sd_kernel,
                         cudaFuncAttributeMaxDynamicSharedMemorySize, GEMM_SMEM);

    gemm_sd_kernel<<<GNBLK, GTPB, GEMM_SMEM>>>(inputs, W, W_attn);
    gat_agg_kernel<<<NN / 8, 256>>>(edges, out);
}